// round 4
// baseline (speedup 1.0000x reference)
#include <cuda_runtime.h>

// Fixed problem shape
constexpr int B_  = 32;
constexpr int C_  = 256;
constexpr int N_  = 4608;         // 96*48
constexpr int N4  = N_ / 4;       // 1152

// Batch split for L2 producer->consumer reuse (75.5 MB/half)
constexpr int SPLITS = 2;
constexpr int BH     = B_ / SPLITS;   // 16

// k1: scalar mapping, one n per thread, double-buffered channel loads
constexpr int K1_THREADS = 128;
constexpr int NT1        = N_ / K1_THREADS;   // 36
constexpr int K1_UNROLL  = 16;

// k3: 8 channels per block, theta staged in shared memory
constexpr int K3_THREADS = 384;
constexpr int CG         = 8;                 // channels per k3 block
constexpr int NCG        = C_ / CG;           // 32 channel-groups

// Scratch (__device__ globals: allocation-free rule)
__device__ float g_theta[B_ * N_];
__device__ float g_partial[B_ * NT1];

// ---------------------------------------------------------------------------
// Kernel 1: per (b,n) channel dots, software-pipelined loads.
// ---------------------------------------------------------------------------
__global__ __launch_bounds__(K1_THREADS)
void k1_dots(const float* __restrict__ x,
             const float* __restrict__ gw, const float* __restrict__ gb,
             const float* __restrict__ tw, const float* __restrict__ tb,
             const float* __restrict__ pw, const float* __restrict__ pb,
             int bbase)
{
    __shared__ float swt[3 * C_];
    const int tid = threadIdx.x;
    for (int i = tid; i < C_; i += K1_THREADS) {
        swt[i]          = gw[i];
        swt[C_ + i]     = tw[i];
        swt[2 * C_ + i] = pw[i];
    }
    __syncthreads();

    const int t = blockIdx.x;
    const int b = bbase + blockIdx.y;
    const int n = t * K1_THREADS + tid;

    const float* xr = x + (size_t)b * C_ * N_ + n;

    float cur[K1_UNROLL], nxt[K1_UNROLL];
    #pragma unroll
    for (int j = 0; j < K1_UNROLL; j++)
        cur[j] = __ldg(xr + (size_t)j * N_);

    float ga = 0.f, ta = 0.f, pa = 0.f;

    #pragma unroll
    for (int c0 = 0; c0 < C_; c0 += K1_UNROLL) {
        if (c0 + K1_UNROLL < C_) {
            #pragma unroll
            for (int j = 0; j < K1_UNROLL; j++)
                nxt[j] = __ldg(xr + (size_t)(c0 + K1_UNROLL + j) * N_);
        }
        #pragma unroll
        for (int j = 0; j < K1_UNROLL; j++) {
            const int c = c0 + j;
            ga = fmaf(swt[c],          cur[j], ga);
            ta = fmaf(swt[C_ + c],     cur[j], ta);
            pa = fmaf(swt[2 * C_ + c], cur[j], pa);
        }
        #pragma unroll
        for (int j = 0; j < K1_UNROLL; j++)
            cur[j] = nxt[j];
    }

    const float gb0 = __ldg(gb), tb0 = __ldg(tb), pb0 = __ldg(pb);

    float pg = (pa + pb0) * (ga + gb0);
    g_theta[(size_t)b * N_ + n] = ta + tb0;

    #pragma unroll
    for (int off = 16; off > 0; off >>= 1)
        pg += __shfl_xor_sync(0xffffffffu, pg, off);

    __shared__ float red[K1_THREADS / 32];
    if ((tid & 31) == 0) red[tid >> 5] = pg;
    __syncthreads();
    if (tid == 0) {
        float s = 0.f;
        #pragma unroll
        for (int w = 0; w < K1_THREADS / 32; w++) s += red[w];
        g_partial[b * NT1 + t] = s;
    }
}

// ---------------------------------------------------------------------------
// Kernel 3: z = theta[b,n]*(s[b]*a[c]) + d[c] + x[b,c,n], 8 c per block.
// Folds in: s[b] from g_partial (fixed order => deterministic), BN coefs.
// ---------------------------------------------------------------------------
__global__ __launch_bounds__(K3_THREADS)
void k3_epilogue(const float* __restrict__ x, float* __restrict__ z,
                 const float* __restrict__ Ww, const float* __restrict__ Wb,
                 const float* __restrict__ gamma, const float* __restrict__ beta,
                 const float* __restrict__ mean,  const float* __restrict__ var,
                 int bbase)
{
    __shared__ float4 sth[N4];          // theta row, 18.4 KB
    __shared__ float  sred[NT1];
    __shared__ float  scA[CG], scD[CG];

    const int tid = threadIdx.x;
    const int cg  = blockIdx.x;
    const int b   = bbase + blockIdx.y;

    // stage theta row
    const float4* th = reinterpret_cast<const float4*>(g_theta) + (size_t)b * N4;
    #pragma unroll
    for (int k = 0; k < N4 / K3_THREADS; k++)
        sth[k * K3_THREADS + tid] = __ldg(th + k * K3_THREADS + tid);

    if (tid < NT1) sred[tid] = g_partial[b * NT1 + tid];
    __syncthreads();

    if (tid < CG) {
        float s = 0.f;
        #pragma unroll
        for (int t = 0; t < NT1; t++) s += sred[t];   // fixed order
        s /= (float)N_;
        const int c = cg * CG + tid;
        const float inv = __ldg(gamma + c) * rsqrtf(__ldg(var + c) + 1e-5f);
        scA[tid] = s * __ldg(Ww + c) * inv;
        scD[tid] = (__ldg(Wb + c) - __ldg(mean + c)) * inv + __ldg(beta + c);
    }
    __syncthreads();

    #pragma unroll
    for (int j = 0; j < CG; j++) {
        const float ca = scA[j];
        const float cd = scD[j];
        const size_t row = ((size_t)b * C_ + cg * CG + j) * N4;
        const float4* xr = reinterpret_cast<const float4*>(x) + row;
        float4*       zr = reinterpret_cast<float4*>(z) + row;
        #pragma unroll
        for (int k = 0; k < N4 / K3_THREADS; k++) {
            const int i = k * K3_THREADS + tid;
            const float4 tv = sth[i];
            const float4 xv = __ldcs(xr + i);      // last use: evict-first
            float4 o;
            o.x = fmaf(tv.x, ca, cd) + xv.x;
            o.y = fmaf(tv.y, ca, cd) + xv.y;
            o.z = fmaf(tv.z, ca, cd) + xv.z;
            o.w = fmaf(tv.w, ca, cd) + xv.w;
            __stcs(zr + i, o);                     // streaming store
        }
    }
}

// ---------------------------------------------------------------------------
extern "C" void kernel_launch(void* const* d_in, const int* in_sizes, int n_in,
                              void* d_out, int out_size)
{
    const float* x     = (const float*)d_in[0];
    const float* g_w   = (const float*)d_in[1];
    const float* g_b   = (const float*)d_in[2];
    const float* th_w  = (const float*)d_in[3];
    const float* th_b  = (const float*)d_in[4];
    const float* ph_w  = (const float*)d_in[5];
    const float* ph_b  = (const float*)d_in[6];
    const float* W_w   = (const float*)d_in[7];
    const float* W_b   = (const float*)d_in[8];
    const float* gamma = (const float*)d_in[9];
    const float* beta  = (const float*)d_in[10];
    const float* mean  = (const float*)d_in[11];
    const float* var   = (const float*)d_in[12];
    float* z = (float*)d_out;

    for (int h = 0; h < SPLITS; h++) {
        const int bbase = h * BH;
        dim3 g1(NT1, BH);
        k1_dots<<<g1, K1_THREADS>>>(x, g_w, g_b, th_w, th_b, ph_w, ph_b, bbase);
        dim3 g3(NCG, BH);
        k3_epilogue<<<g3, K3_THREADS>>>(x, z, W_w, W_b, gamma, beta, mean, var, bbase);
    }
}

// round 5
// speedup vs baseline: 1.0682x; 1.0682x over previous
#include <cuda_runtime.h>

// Fixed problem shape
constexpr int B_  = 32;
constexpr int C_  = 256;
constexpr int N_  = 4608;         // 96*48
constexpr int N4  = N_ / 4;       // 1152

// Batch split for L2 producer->consumer reuse (75.5 MB/half)
constexpr int SPLITS = 2;
constexpr int BH     = B_ / SPLITS;   // 16

// k1: one n per thread, C split into halves across blocks
constexpr int K1_THREADS = 128;
constexpr int NT1        = N_ / K1_THREADS;   // 36
constexpr int CH         = 2;                 // channel halves
constexpr int CHC        = C_ / CH;           // 128 channels per block
constexpr int K1_UNROLL  = 16;

// k2: per-batch merge + reduce
constexpr int K2_THREADS = 256;
constexpr int K2_ITERS   = N_ / K2_THREADS;   // 18

// k3: one (b,c) row per block
constexpr int K3_THREADS = 384;

// Scratch (__device__ globals: allocation-free rule)
__device__ float g_gh[CH][B_ * N_];    // partial g dots
__device__ float g_ph[CH][B_ * N_];    // partial phi dots
__device__ float g_th[CH][B_ * N_];    // partial theta dots
__device__ float g_theta[B_ * N_];     // merged theta (+bias)
__device__ float g_s[B_];

// ---------------------------------------------------------------------------
// Kernel 1: partial channel dots over a 128-channel half. No reductions.
// ---------------------------------------------------------------------------
__global__ __launch_bounds__(K1_THREADS)
void k1_dots(const float* __restrict__ x,
             const float* __restrict__ gw,
             const float* __restrict__ tw,
             const float* __restrict__ pw,
             int bbase)
{
    __shared__ float swt[3 * CHC];
    const int tid = threadIdx.x;
    const int ch  = blockIdx.y;            // channel half
    for (int i = tid; i < CHC; i += K1_THREADS) {
        swt[i]           = gw[ch * CHC + i];
        swt[CHC + i]     = tw[ch * CHC + i];
        swt[2 * CHC + i] = pw[ch * CHC + i];
    }
    __syncthreads();

    const int t = blockIdx.x;
    const int b = bbase + blockIdx.z;
    const int n = t * K1_THREADS + tid;

    const float* xr = x + ((size_t)b * C_ + (size_t)ch * CHC) * N_ + n;

    float ga = 0.f, ta = 0.f, pa = 0.f;

    #pragma unroll
    for (int c0 = 0; c0 < CHC; c0 += K1_UNROLL) {
        float xv[K1_UNROLL];
        #pragma unroll
        for (int j = 0; j < K1_UNROLL; j++)
            xv[j] = __ldg(xr + (size_t)(c0 + j) * N_);
        #pragma unroll
        for (int j = 0; j < K1_UNROLL; j++) {
            const int c = c0 + j;
            ga = fmaf(swt[c],           xv[j], ga);
            ta = fmaf(swt[CHC + c],     xv[j], ta);
            pa = fmaf(swt[2 * CHC + c], xv[j], pa);
        }
    }

    const size_t o = (size_t)b * N_ + n;
    g_gh[ch][o] = ga;
    g_th[ch][o] = ta;
    g_ph[ch][o] = pa;
}

// ---------------------------------------------------------------------------
// Kernel 2: per batch — merge theta halves (+bias), compute s[b].
// All inputs are L2-resident partials. Deterministic reduction order.
// ---------------------------------------------------------------------------
__global__ __launch_bounds__(K2_THREADS)
void k2_merge(const float* __restrict__ gb, const float* __restrict__ tb,
              const float* __restrict__ pb, int bbase)
{
    const int b   = bbase + blockIdx.x;
    const int tid = threadIdx.x;
    const float gb0 = __ldg(gb), tb0 = __ldg(tb), pb0 = __ldg(pb);

    float s = 0.f;
    #pragma unroll
    for (int k = 0; k < K2_ITERS; k++) {
        const size_t o = (size_t)b * N_ + k * K2_THREADS + tid;
        const float gv = g_gh[0][o] + g_gh[1][o] + gb0;
        const float pv = g_ph[0][o] + g_ph[1][o] + pb0;
        g_theta[o] = g_th[0][o] + g_th[1][o] + tb0;
        s = fmaf(gv, pv, s);
    }

    #pragma unroll
    for (int off = 16; off > 0; off >>= 1)
        s += __shfl_xor_sync(0xffffffffu, s, off);

    __shared__ float red[K2_THREADS / 32];
    if ((tid & 31) == 0) red[tid >> 5] = s;
    __syncthreads();
    if (tid == 0) {
        float acc = 0.f;
        #pragma unroll
        for (int w = 0; w < K2_THREADS / 32; w++) acc += red[w];
        g_s[b] = acc / (float)N_;
    }
}

// ---------------------------------------------------------------------------
// Kernel 3: z = theta[b,n]*ca + cd + x[b,c,n], one (b,c) row per block.
// Coefs computed redundantly per thread (broadcast L2 loads, no sync).
// ---------------------------------------------------------------------------
__global__ __launch_bounds__(K3_THREADS)
void k3_epilogue(const float* __restrict__ x, float* __restrict__ z,
                 const float* __restrict__ Ww, const float* __restrict__ Wb,
                 const float* __restrict__ gamma, const float* __restrict__ beta,
                 const float* __restrict__ mean,  const float* __restrict__ var,
                 int bbase)
{
    const int c = blockIdx.x;
    const int b = bbase + blockIdx.y;

    const float inv = __ldg(gamma + c) * rsqrtf(__ldg(var + c) + 1e-5f);
    const float ca  = g_s[b] * __ldg(Ww + c) * inv;
    const float cd  = (__ldg(Wb + c) - __ldg(mean + c)) * inv + __ldg(beta + c);

    const size_t row = ((size_t)b * C_ + c) * N4;
    const float4* xr = reinterpret_cast<const float4*>(x) + row;
    float4*       zr = reinterpret_cast<float4*>(z) + row;
    const float4* th = reinterpret_cast<const float4*>(g_theta) + (size_t)b * N4;

    #pragma unroll
    for (int k = 0; k < N4 / K3_THREADS; k++) {
        const int i = k * K3_THREADS + threadIdx.x;
        const float4 tv = __ldg(th + i);
        const float4 xv = __ldcs(xr + i);
        float4 o;
        o.x = fmaf(tv.x, ca, cd) + xv.x;
        o.y = fmaf(tv.y, ca, cd) + xv.y;
        o.z = fmaf(tv.z, ca, cd) + xv.z;
        o.w = fmaf(tv.w, ca, cd) + xv.w;
        __stcs(zr + i, o);
    }
}

// ---------------------------------------------------------------------------
extern "C" void kernel_launch(void* const* d_in, const int* in_sizes, int n_in,
                              void* d_out, int out_size)
{
    const float* x     = (const float*)d_in[0];
    const float* g_w   = (const float*)d_in[1];
    const float* g_b   = (const float*)d_in[2];
    const float* th_w  = (const float*)d_in[3];
    const float* th_b  = (const float*)d_in[4];
    const float* ph_w  = (const float*)d_in[5];
    const float* ph_b  = (const float*)d_in[6];
    const float* W_w   = (const float*)d_in[7];
    const float* W_b   = (const float*)d_in[8];
    const float* gamma = (const float*)d_in[9];
    const float* beta  = (const float*)d_in[10];
    const float* mean  = (const float*)d_in[11];
    const float* var   = (const float*)d_in[12];
    float* z = (float*)d_out;

    for (int h = 0; h < SPLITS; h++) {
        const int bbase = h * BH;
        dim3 g1(NT1, CH, BH);
        k1_dots<<<g1, K1_THREADS>>>(x, g_w, th_w, ph_w, bbase);
        k2_merge<<<BH, K2_THREADS>>>(g_b, th_b, ph_b, bbase);
        dim3 g3(C_, BH);
        k3_epilogue<<<g3, K3_THREADS>>>(x, z, W_w, W_b, gamma, beta, mean, var, bbase);
    }
}